// round 3
// baseline (speedup 1.0000x reference)
#include <cuda_runtime.h>
#include <math.h>

// Problem constants (fixed by the dataset instance):
// B=8, A=1024, N=64, G=50, F=128
#define A_DIM 1024
#define N_DIM 64
#define G_DIM 50
#define F_DIM 128
#define NT    16           // neighbors processed per pass
#define HPAD  20           // padded row stride (floats) for h_sh: 80B -> 16B aligned, conflict-free .128
#define LOG2F_CONST 0.6931471805599453f

// Scratch for xw = x @ W_in2f  (B*A*F = 8*1024*128 floats = 4 MB)
__device__ float g_xw[8 * A_DIM * F_DIM];

__device__ __forceinline__ float ssp(float x) {
    // shifted softplus: log1p(exp(x)) - log(2), numerically stable
    float sp = fmaxf(x, 0.0f) + log1pf(__expf(-fabsf(x)));
    return sp - LOG2F_CONST;
}

// ---------------------------------------------------------------------------
// Kernel 1: xw[row, o] = sum_c x[row, c] * W_in2f[c, o]
// One block per row (B*A rows), 128 threads, thread = output channel o.
// ---------------------------------------------------------------------------
__global__ __launch_bounds__(F_DIM) void xw_kernel(
    const float* __restrict__ x,
    const float* __restrict__ W_in2f)
{
    __shared__ float xs[F_DIM];
    const int row = blockIdx.x;
    const int o   = threadIdx.x;

    xs[o] = x[(size_t)row * F_DIM + o];
    __syncthreads();

    float acc = 0.0f;
#pragma unroll 8
    for (int c = 0; c < F_DIM; ++c)
        acc = fmaf(xs[c], __ldg(&W_in2f[c * F_DIM + o]), acc);

    g_xw[(size_t)row * F_DIM + o] = acc;
}

// ---------------------------------------------------------------------------
// Kernel 2: fused CFConv main.
// One block per (b, a) atom. 128 threads; thread f owns channel f.
// Per pass of NT=16 neighbors:
//   phase 1: stage f_ij[16][50], neighbor idx, mask into shared
//   phase 2: h[n] = ssp(f_ij[n,:] @ W_f1[:,f] + b1[f])  (regs), store to h_sh
//   phase 3: w[n] = h_sh[:,n] @ W_f2[:,f] + b2[f]; gather xw[nbr]; accumulate
// Epilogue: out[f] = ssp(acc[:] @ W_f2out[:,f] + b_out[f])
// ---------------------------------------------------------------------------
__global__ __launch_bounds__(F_DIM) void cfconv_kernel(
    const float* __restrict__ f_ij,     // [B,A,N,G]
    const float* __restrict__ mask,     // [B,A,N]
    const int*   __restrict__ nbrs,     // [B,A,N]
    const float* __restrict__ W_f1,     // [G,F]
    const float* __restrict__ b_f1,     // [F]
    const float* __restrict__ W_f2,     // [F,F]
    const float* __restrict__ b_f2,     // [F]
    const float* __restrict__ W_out,    // [F,F]
    const float* __restrict__ b_out,    // [F]
    float*       __restrict__ out)      // [B,A,F]
{
    __shared__ float fij_sh[NT][G_DIM];     // 3200 B
    __shared__ float h_sh[F_DIM][HPAD];     // 10240 B (padded, .128-friendly)
    __shared__ float acc_sh[F_DIM];
    __shared__ int   nbr_sh[NT];
    __shared__ float msk_sh[NT];

    const int ba = blockIdx.x;
    const int b  = ba >> 10;                 // / A_DIM
    const int f  = threadIdx.x;

    const float* fij_base = f_ij + (size_t)ba * N_DIM * G_DIM;
    const int*   nbr_base = nbrs + (size_t)ba * N_DIM;
    const float* msk_base = mask + (size_t)ba * N_DIM;
    const float* xw_b     = g_xw + (size_t)b * A_DIM * F_DIM;

    const float b1 = b_f1[f];
    const float b2 = b_f2[f];

    float acc = 0.0f;

    for (int n0 = 0; n0 < N_DIM; n0 += NT) {
        __syncthreads();   // protect shared-tile reuse from previous pass

        // ---- phase 1: stage inputs ----
#pragma unroll
        for (int i = f; i < NT * G_DIM; i += F_DIM) {
            int n = i / G_DIM, g = i % G_DIM;
            fij_sh[n][g] = fij_base[(size_t)(n0 + n) * G_DIM + g];
        }
        if (f < NT) {
            nbr_sh[f] = nbr_base[n0 + f];
            msk_sh[f] = msk_base[n0 + f];
        }
        __syncthreads();

        // ---- phase 2: h[n] = ssp(f_ij @ W_f1 + b1), column f ----
        float h[NT];
#pragma unroll
        for (int n = 0; n < NT; ++n) h[n] = b1;

#pragma unroll 5
        for (int g = 0; g < G_DIM; ++g) {
            float w = __ldg(&W_f1[g * F_DIM + f]);   // coalesced; L1-resident
#pragma unroll
            for (int n = 0; n < NT; ++n)
                h[n] = fmaf(fij_sh[n][g], w, h[n]);
        }
#pragma unroll
        for (int n = 0; n < NT; ++n) h[n] = ssp(h[n]);

        // store as 4x float4 (row f, stride HPAD=20 floats -> 16B aligned)
        {
            float4* rp = reinterpret_cast<float4*>(&h_sh[f][0]);
            rp[0] = make_float4(h[0],  h[1],  h[2],  h[3]);
            rp[1] = make_float4(h[4],  h[5],  h[6],  h[7]);
            rp[2] = make_float4(h[8],  h[9],  h[10], h[11]);
            rp[3] = make_float4(h[12], h[13], h[14], h[15]);
        }
        __syncthreads();

        // ---- phase 3: w[n] = h @ W_f2 + b2, column f; then gather-multiply ----
        float wv[NT];
#pragma unroll
        for (int n = 0; n < NT; ++n) wv[n] = b2;

#pragma unroll 2
        for (int k = 0; k < F_DIM; ++k) {
            float w = __ldg(&W_f2[k * F_DIM + f]);   // coalesced; L1-resident
            const float4* hp = reinterpret_cast<const float4*>(&h_sh[k][0]);
            float4 h0 = hp[0], h1 = hp[1], h2 = hp[2], h3 = hp[3]; // broadcast LDS
            wv[0]  = fmaf(h0.x, w, wv[0]);  wv[1]  = fmaf(h0.y, w, wv[1]);
            wv[2]  = fmaf(h0.z, w, wv[2]);  wv[3]  = fmaf(h0.w, w, wv[3]);
            wv[4]  = fmaf(h1.x, w, wv[4]);  wv[5]  = fmaf(h1.y, w, wv[5]);
            wv[6]  = fmaf(h1.z, w, wv[6]);  wv[7]  = fmaf(h1.w, w, wv[7]);
            wv[8]  = fmaf(h2.x, w, wv[8]);  wv[9]  = fmaf(h2.y, w, wv[9]);
            wv[10] = fmaf(h2.z, w, wv[10]); wv[11] = fmaf(h2.w, w, wv[11]);
            wv[12] = fmaf(h3.x, w, wv[12]); wv[13] = fmaf(h3.y, w, wv[13]);
            wv[14] = fmaf(h3.z, w, wv[14]); wv[15] = fmaf(h3.w, w, wv[15]);
        }

#pragma unroll
        for (int n = 0; n < NT; ++n) {
            int   nb = nbr_sh[n];
            float xv = __ldg(&xw_b[(size_t)nb * F_DIM + f]);  // L2-resident gather
            acc = fmaf(wv[n] * msk_sh[n], xv, acc);
        }
    }

    // ---- epilogue: out = ssp(acc @ W_f2out + b_out) ----
    __syncthreads();
    acc_sh[f] = acc;
    __syncthreads();

    float o = b_out[f];
#pragma unroll 8
    for (int c = 0; c < F_DIM; ++c)
        o = fmaf(acc_sh[c], __ldg(&W_out[c * F_DIM + f]), o);

    out[(size_t)ba * F_DIM + f] = ssp(o);
}

// ---------------------------------------------------------------------------
// Launch
// Input order: x, pairwise_mask, neighbors, f_ij, W_f1, b_f1, W_f2, b_f2,
//              W_in2f, W_f2out, b_f2out
// ---------------------------------------------------------------------------
extern "C" void kernel_launch(void* const* d_in, const int* in_sizes, int n_in,
                              void* d_out, int out_size)
{
    const float* x      = (const float*)d_in[0];
    const float* mask   = (const float*)d_in[1];
    const int*   nbrs   = (const int*)  d_in[2];
    const float* f_ij   = (const float*)d_in[3];
    const float* W_f1   = (const float*)d_in[4];
    const float* b_f1   = (const float*)d_in[5];
    const float* W_f2   = (const float*)d_in[6];
    const float* b_f2   = (const float*)d_in[7];
    const float* W_in2f = (const float*)d_in[8];
    const float* W_out  = (const float*)d_in[9];
    const float* b_out  = (const float*)d_in[10];
    float*       out    = (float*)d_out;

    const int BA = in_sizes[0] / F_DIM;   // B*A = 8192

    xw_kernel<<<BA, F_DIM>>>(x, W_in2f);
    cfconv_kernel<<<BA, F_DIM>>>(f_ij, mask, nbrs,
                                 W_f1, b_f1, W_f2, b_f2,
                                 W_out, b_out, out);
}

// round 5
// speedup vs baseline: 2.4874x; 2.4874x over previous
#include <cuda_runtime.h>
#include <math.h>
#include <cstdint>

// B=8, A=1024, N=64, G=50, F=128
#define A_DIM 1024
#define F_DIM 128
#define G_DIM 50
#define LOG2F_CONST 0.6931471805599453f

// ---------------- device scratch ----------------
__device__ float g_xw[8 * A_DIM * F_DIM];     // x @ W_in2f  (4 MB)
__device__ float g_y [8 * A_DIM * F_DIM];     // pre-output  (4 MB)
__device__ float g_Wf1p[64 * F_DIM];          // W_f1 zero-padded to K=64, tf32-rounded
__device__ float g_Wf2p[F_DIM * F_DIM];       // W_f2 tf32-rounded

__device__ __forceinline__ float ssp(float x) {
    // log(1+e^x) - log2 = max(x,0) + log(1+e^-|x|) - log2
    return fmaxf(x, 0.0f) + __logf(1.0f + __expf(-fabsf(x))) - LOG2F_CONST;
}
__device__ __forceinline__ float tf32r(float x) {
    uint32_t r;
    asm("cvt.rna.tf32.f32 %0, %1;" : "=r"(r) : "f"(x));
    return __uint_as_float(r);
}

// m16n8k8 row.col tf32 MMA. Fragment mapping (lane: gid=lane>>2, tig=lane&3):
//   A: a0=(gid,tig) a1=(gid+8,tig) a2=(gid,tig+4) a3=(gid+8,tig+4)
//   B: b0=(tig,gid) b1=(tig+4,gid)        [row=k, col=n]
//   D: d0=(gid,2tig) d1=(gid,2tig+1) d2=(gid+8,2tig) d3=(gid+8,2tig+1)
__device__ __forceinline__ void mma8(float* d, const uint32_t* a, const uint32_t* b) {
    asm volatile(
        "mma.sync.aligned.m16n8k8.row.col.f32.tf32.tf32.f32 "
        "{%0,%1,%2,%3}, {%4,%5,%6,%7}, {%8,%9}, {%0,%1,%2,%3};"
        : "+f"(d[0]), "+f"(d[1]), "+f"(d[2]), "+f"(d[3])
        : "r"(a[0]), "r"(a[1]), "r"(a[2]), "r"(a[3]), "r"(b[0]), "r"(b[1]));
}

// ---------------- SMEM layout ----------------
#define FS1 68            // f_ij row stride (floats): bank = (4n+k)%32, A-pattern conflict-free
#define HS  132           // h row stride (floats):   bank = (4n+k)%32, A-pattern conflict-free
#define OFF_B1   0        // b_f1   [128]f
#define OFF_B2   512      // b_f2   [128]f
#define OFF_NBR  1024     // nbr    [128]i
#define OFF_MSK  1536     // mask   [128]f
#define OFF_FIJ  2048     // f_ij   [128][68]f = 34816
#define OFF_H    36864    // h / Wm [128][132]f = 67584
#define SMEM_TOTAL 104448

// ---------------------------------------------------------------------------
// prep: tf32-round + pad weights
// ---------------------------------------------------------------------------
__global__ void prep_kernel(const float* __restrict__ W_f1, const float* __restrict__ W_f2) {
    int t = threadIdx.x;
    for (int i = t; i < 64 * F_DIM; i += blockDim.x) {
        int k = i >> 7;
        g_Wf1p[i] = (k < G_DIM) ? tf32r(W_f1[i]) : 0.0f;   // same [k][f] layout
    }
    for (int i = t; i < F_DIM * F_DIM; i += blockDim.x)
        g_Wf2p[i] = tf32r(W_f2[i]);
}

// ---------------------------------------------------------------------------
// dense: out[r, o] = (ssp?)(in[r,:] @ W[:,o] + bias)   — 4 rows per CTA
// ---------------------------------------------------------------------------
__global__ __launch_bounds__(F_DIM) void dense_kernel(
    const float* __restrict__ in, const float* __restrict__ W,
    const float* __restrict__ bias, float* __restrict__ outp, int apply_ssp)
{
    __shared__ float xs[4 * F_DIM];
    const int r0 = blockIdx.x * 4, o = threadIdx.x;
#pragma unroll
    for (int r = 0; r < 4; ++r)
        xs[r * F_DIM + o] = in[(size_t)(r0 + r) * F_DIM + o];
    __syncthreads();

    float a0, a1, a2, a3;
    a0 = a1 = a2 = a3 = bias ? __ldg(&bias[o]) : 0.0f;
#pragma unroll 4
    for (int c = 0; c < F_DIM; ++c) {
        float w = __ldg(&W[c * F_DIM + o]);
        a0 = fmaf(xs[c], w, a0);
        a1 = fmaf(xs[F_DIM + c], w, a1);
        a2 = fmaf(xs[2 * F_DIM + c], w, a2);
        a3 = fmaf(xs[3 * F_DIM + c], w, a3);
    }
    if (apply_ssp) { a0 = ssp(a0); a1 = ssp(a1); a2 = ssp(a2); a3 = ssp(a3); }
    outp[(size_t)(r0 + 0) * F_DIM + o] = a0;
    outp[(size_t)(r0 + 1) * F_DIM + o] = a1;
    outp[(size_t)(r0 + 2) * F_DIM + o] = a2;
    outp[(size_t)(r0 + 3) * F_DIM + o] = a3;
}

// ---------------------------------------------------------------------------
// Main: one CTA per 2 atoms (128 neighbor rows), 256 threads, 8 warps.
//   GEMM1 (mma tf32): D1[n,f] = f_ij[n,g(64)] @ Wf1p[g,f]
//   epi1 : h = tf32(ssp(D1 + b1)) -> SMEM
//   GEMM2 (mma tf32): D2[n,k] = h[n,f] @ Wf2p[f,k]
//   epi2 : Wm[n,k] = (D2 + b2[k]) * mask[n] -> SMEM (reuse h)
//   reduce: y[atom,f] = sum_n Wm[n,f] * xw[nbr[n], f]   (coalesced gather)
// ---------------------------------------------------------------------------
__global__ __launch_bounds__(256) void cfconv_mma(
    const float* __restrict__ f_ij,   // [B,A,N,G]
    const float* __restrict__ mask,   // [B,A,N]
    const int*   __restrict__ nbrs,   // [B,A,N]
    const float* __restrict__ b_f1,
    const float* __restrict__ b_f2)
{
    extern __shared__ char smem[];
    float* b1s    = (float*)(smem + OFF_B1);
    float* b2s    = (float*)(smem + OFF_B2);
    int*   nbr_sh = (int*)  (smem + OFF_NBR);
    float* msk_sh = (float*)(smem + OFF_MSK);
    float* fij_s  = (float*)(smem + OFF_FIJ);
    float* h_s    = (float*)(smem + OFF_H);

    const int tid = threadIdx.x, wid = tid >> 5, lane = tid & 31;
    const int gid = lane >> 2, tig = lane & 3;
    const int c = blockIdx.x;          // atoms 2c, 2c+1
    const int b = c >> 9;              // batch

    if (tid < 128) {
        b1s[tid]    = b_f1[tid];
        b2s[tid]    = b_f2[tid];
        nbr_sh[tid] = nbrs[(size_t)c * 128 + tid];
        msk_sh[tid] = mask[(size_t)c * 128 + tid];
    }
    // stage f_ij tile [128 rows][64 cols], tf32-rounded, zero-padded
    {
        const float* fb = f_ij + (size_t)c * 128 * G_DIM;
        for (int i = tid; i < 128 * 64; i += 256) {
            int r = i >> 6, cc = i & 63;
            fij_s[r * FS1 + cc] = (cc < G_DIM) ? tf32r(__ldg(fb + r * G_DIM + cc)) : 0.0f;
        }
    }
    __syncthreads();

    const int n0 = (wid & 3) * 32;     // warp's 32 rows
    const int f0 = (wid >> 2) * 64;    // warp's 64 cols

    // ================= GEMM1: K=64 =================
    float acc[16][4];
#pragma unroll
    for (int t = 0; t < 16; ++t) { acc[t][0]=acc[t][1]=acc[t][2]=acc[t][3]=0.f; }

    const uint32_t* fij_u = (const uint32_t*)fij_s;
#pragma unroll
    for (int ks = 0; ks < 8; ++ks) {
        const int k0 = ks * 8;
        uint32_t a[2][4], bf[8][2];
#pragma unroll
        for (int mi = 0; mi < 2; ++mi) {
            int r = (n0 + mi * 16 + gid) * FS1 + k0 + tig;
            a[mi][0] = fij_u[r];
            a[mi][1] = fij_u[r + 8 * FS1];
            a[mi][2] = fij_u[r + 4];
            a[mi][3] = fij_u[r + 8 * FS1 + 4];
        }
#pragma unroll
        for (int ni = 0; ni < 8; ++ni) {
            int col = f0 + ni * 8 + gid;
            bf[ni][0] = __float_as_uint(__ldg(&g_Wf1p[(k0 + tig)     * F_DIM + col]));
            bf[ni][1] = __float_as_uint(__ldg(&g_Wf1p[(k0 + tig + 4) * F_DIM + col]));
        }
#pragma unroll
        for (int mi = 0; mi < 2; ++mi)
#pragma unroll
            for (int ni = 0; ni < 8; ++ni)
                mma8(acc[mi * 8 + ni], a[mi], bf[ni]);
    }

    // ---- epi1: h = tf32(ssp(D1 + b1)) ----
#pragma unroll
    for (int mi = 0; mi < 2; ++mi)
#pragma unroll
        for (int ni = 0; ni < 8; ++ni) {
            float* d = acc[mi * 8 + ni];
            int f = f0 + ni * 8 + 2 * tig;
            int n = n0 + mi * 16 + gid;
            float bb0 = b1s[f], bb1 = b1s[f + 1];
            float2 v0 = make_float2(tf32r(ssp(d[0] + bb0)), tf32r(ssp(d[1] + bb1)));
            float2 v1 = make_float2(tf32r(ssp(d[2] + bb0)), tf32r(ssp(d[3] + bb1)));
            *(float2*)&h_s[n * HS + f]       = v0;
            *(float2*)&h_s[(n + 8) * HS + f] = v1;
        }
    __syncthreads();

    // ================= GEMM2: K=128 =================
#pragma unroll
    for (int t = 0; t < 16; ++t) { acc[t][0]=acc[t][1]=acc[t][2]=acc[t][3]=0.f; }

    const uint32_t* h_u = (const uint32_t*)h_s;
#pragma unroll
    for (int ks = 0; ks < 16; ++ks) {
        const int k0 = ks * 8;
        uint32_t a[2][4], bf[8][2];
#pragma unroll
        for (int mi = 0; mi < 2; ++mi) {
            int r = (n0 + mi * 16 + gid) * HS + k0 + tig;
            a[mi][0] = h_u[r];
            a[mi][1] = h_u[r + 8 * HS];
            a[mi][2] = h_u[r + 4];
            a[mi][3] = h_u[r + 8 * HS + 4];
        }
#pragma unroll
        for (int ni = 0; ni < 8; ++ni) {
            int col = f0 + ni * 8 + gid;
            bf[ni][0] = __float_as_uint(__ldg(&g_Wf2p[(k0 + tig)     * F_DIM + col]));
            bf[ni][1] = __float_as_uint(__ldg(&g_Wf2p[(k0 + tig + 4) * F_DIM + col]));
        }
#pragma unroll
        for (int mi = 0; mi < 2; ++mi)
#pragma unroll
            for (int ni = 0; ni < 8; ++ni)
                mma8(acc[mi * 8 + ni], a[mi], bf[ni]);
    }
    __syncthreads();   // all warps done reading h before overwrite

    // ---- epi2: Wm = (D2 + b2) * mask -> SMEM (reuse h region) ----
#pragma unroll
    for (int mi = 0; mi < 2; ++mi)
#pragma unroll
        for (int ni = 0; ni < 8; ++ni) {
            float* d = acc[mi * 8 + ni];
            int f = f0 + ni * 8 + 2 * tig;
            int n = n0 + mi * 16 + gid;
            float bb0 = b2s[f], bb1 = b2s[f + 1];
            float m0 = msk_sh[n], m1 = msk_sh[n + 8];
            *(float2*)&h_s[n * HS + f]       = make_float2((d[0] + bb0) * m0, (d[1] + bb1) * m0);
            *(float2*)&h_s[(n + 8) * HS + f] = make_float2((d[2] + bb0) * m1, (d[3] + bb1) * m1);
        }
    __syncthreads();

    // ---- reduce: y[atom, f] = sum_n Wm[n,f] * xw[nbr[n], f] ----
    {
        const int at = tid >> 7, f = tid & 127;
        const float* xwb = g_xw + (size_t)b * A_DIM * F_DIM + f;
        float y = 0.0f;
#pragma unroll 8
        for (int j = 0; j < 64; ++j) {
            int n = at * 64 + j;
            float xv = __ldg(xwb + (size_t)nbr_sh[n] * F_DIM);
            y = fmaf(h_s[n * HS + f], xv, y);
        }
        g_y[(size_t)(c * 2 + at) * F_DIM + f] = y;
    }
}

// ---------------------------------------------------------------------------
// Inputs: x, pairwise_mask, neighbors, f_ij, W_f1, b_f1, W_f2, b_f2,
//         W_in2f, W_f2out, b_f2out
// ---------------------------------------------------------------------------
extern "C" void kernel_launch(void* const* d_in, const int* in_sizes, int n_in,
                              void* d_out, int out_size)
{
    const float* x      = (const float*)d_in[0];
    const float* mask   = (const float*)d_in[1];
    const int*   nbrs   = (const int*)  d_in[2];
    const float* f_ij   = (const float*)d_in[3];
    const float* W_f1   = (const float*)d_in[4];
    const float* b_f1   = (const float*)d_in[5];
    const float* W_f2   = (const float*)d_in[6];
    const float* b_f2   = (const float*)d_in[7];
    const float* W_in2f = (const float*)d_in[8];
    const float* W_out  = (const float*)d_in[9];
    const float* b_out  = (const float*)d_in[10];
    float*       out    = (float*)d_out;

    const int BA = in_sizes[0] / F_DIM;   // 8192

    static float* xw_ptr = nullptr;
    static float* y_ptr  = nullptr;
    if (!xw_ptr) { cudaGetSymbolAddress((void**)&xw_ptr, g_xw);
                   cudaGetSymbolAddress((void**)&y_ptr,  g_y); }

    cudaFuncSetAttribute(cfconv_mma, cudaFuncAttributeMaxDynamicSharedMemorySize, SMEM_TOTAL);

    prep_kernel<<<1, 256>>>(W_f1, W_f2);
    dense_kernel<<<BA / 4, F_DIM>>>(x, W_in2f, nullptr, xw_ptr, 0);     // xw = x @ W_in2f
    cfconv_mma<<<BA / 2, 256, SMEM_TOTAL>>>(f_ij, mask, nbrs, b_f1, b_f2);
    dense_kernel<<<BA / 4, F_DIM>>>(y_ptr, W_out, b_out, out, 1);       // out = ssp(y @ W_out + b)
}